// round 3
// baseline (speedup 1.0000x reference)
#include <cuda_runtime.h>
#include <math.h>

#define BATCH  4
#define NQ     1024
#define NK     1024
#define DMODEL 512
#define NHEAD  8
#define DHEAD  64
#define LN_EPS 1e-5f

// ---------------- scratch (device globals: allocation-free) ----------------
__device__ float g_Q[(size_t)BATCH * NQ * DMODEL];
__device__ float g_K[(size_t)BATCH * NK * DMODEL];
__device__ float g_V[(size_t)BATCH * NK * DMODEL];
__device__ float g_ctx[(size_t)BATCH * NQ * DMODEL];
__device__ float g_x[(size_t)BATCH * NQ * DMODEL];
// fallback for w if harness only expects the LN output
__device__ float g_w_fb[(size_t)BATCH * NHEAD * NQ * NK];

// ---------------- generic tiled GEMM: C = A[MxK] @ B[KxN] + bias ----------
// BM=BN=64, BK=16, 256 threads, 4x4 per-thread micro-tile.
__global__ void gemm_bias_kernel(const float* __restrict__ A,
                                 const float* __restrict__ B,
                                 const float* __restrict__ bias,
                                 float* __restrict__ C,
                                 int M, int N, int K)
{
    __shared__ float As[16][64];
    __shared__ float Bs[16][64];
    const int tid = threadIdx.x;
    const int tx = tid & 15, ty = tid >> 4;
    const int row0 = blockIdx.y * 64;
    const int col0 = blockIdx.x * 64;

    float acc[4][4] = {};
    for (int k0 = 0; k0 < K; k0 += 16) {
        // A tile 64x16 (transpose into As[k][m])
        {
            int r  = tid >> 2;
            int c4 = (tid & 3) << 2;
            float4 v = *reinterpret_cast<const float4*>(
                &A[(size_t)(row0 + r) * K + k0 + c4]);
            As[c4 + 0][r] = v.x; As[c4 + 1][r] = v.y;
            As[c4 + 2][r] = v.z; As[c4 + 3][r] = v.w;
        }
        // B tile 16x64
        {
            int r  = tid >> 4;
            int c4 = (tid & 15) << 2;
            float4 v = *reinterpret_cast<const float4*>(
                &B[(size_t)(k0 + r) * N + col0 + c4]);
            *reinterpret_cast<float4*>(&Bs[r][c4]) = v;
        }
        __syncthreads();
        #pragma unroll
        for (int kk = 0; kk < 16; kk++) {
            float4 a = *reinterpret_cast<const float4*>(&As[kk][ty * 4]);
            float4 b = *reinterpret_cast<const float4*>(&Bs[kk][tx * 4]);
            const float av[4] = {a.x, a.y, a.z, a.w};
            const float bv[4] = {b.x, b.y, b.z, b.w};
            #pragma unroll
            for (int i = 0; i < 4; i++)
                #pragma unroll
                for (int j = 0; j < 4; j++)
                    acc[i][j] += av[i] * bv[j];
        }
        __syncthreads();
    }
    #pragma unroll
    for (int i = 0; i < 4; i++) {
        int r = row0 + ty * 4 + i;
        #pragma unroll
        for (int j = 0; j < 4; j++) {
            int c = col0 + tx * 4 + j;
            C[(size_t)r * N + c] = acc[i][j] + bias[c];
        }
    }
}

// ------------- attention scores: S = Qh @ Kh^T / 8 + bias, masked ----------
// per block: one 64x64 tile of S for one (b,h). K-dim = DHEAD = 64.
__global__ void scores_kernel(const float* __restrict__ Q,
                              const float* __restrict__ Kmat,
                              const int* __restrict__ mask_k,
                              const float* __restrict__ log_g,
                              float* __restrict__ W)
{
    const int bh = blockIdx.z;
    const int b  = bh / NHEAD, h = bh % NHEAD;
    const float* Ap = Q    + (size_t)b * NQ * DMODEL + h * DHEAD;
    const float* Bp = Kmat + (size_t)b * NK * DMODEL + h * DHEAD;
    const int q0 = blockIdx.y * 64;
    const int k0 = blockIdx.x * 64;

    __shared__ float As[16][64];
    __shared__ float Bs[16][64];
    const int tid = threadIdx.x;
    const int tx = tid & 15, ty = tid >> 4;

    float acc[4][4] = {};
    for (int d0 = 0; d0 < DHEAD; d0 += 16) {
        {
            int r  = tid >> 2;
            int c4 = (tid & 3) << 2;
            float4 v = *reinterpret_cast<const float4*>(
                &Ap[(size_t)(q0 + r) * DMODEL + d0 + c4]);
            As[c4 + 0][r] = v.x; As[c4 + 1][r] = v.y;
            As[c4 + 2][r] = v.z; As[c4 + 3][r] = v.w;
            float4 u = *reinterpret_cast<const float4*>(
                &Bp[(size_t)(k0 + r) * DMODEL + d0 + c4]);
            Bs[c4 + 0][r] = u.x; Bs[c4 + 1][r] = u.y;
            Bs[c4 + 2][r] = u.z; Bs[c4 + 3][r] = u.w;
        }
        __syncthreads();
        #pragma unroll
        for (int kk = 0; kk < 16; kk++) {
            float4 a = *reinterpret_cast<const float4*>(&As[kk][ty * 4]);
            float4 bb = *reinterpret_cast<const float4*>(&Bs[kk][tx * 4]);
            const float av[4] = {a.x, a.y, a.z, a.w};
            const float bv[4] = {bb.x, bb.y, bb.z, bb.w};
            #pragma unroll
            for (int i = 0; i < 4; i++)
                #pragma unroll
                for (int j = 0; j < 4; j++)
                    acc[i][j] += av[i] * bv[j];
        }
        __syncthreads();
    }
    float* Wbh = W + (size_t)bh * NQ * NK;
    #pragma unroll
    for (int j = 0; j < 4; j++) {
        int k = k0 + tx * 4 + j;
        float bias = log_g[b * NK + k];
        bool  m    = mask_k[b * NK + k] != 0;
        #pragma unroll
        for (int i = 0; i < 4; i++) {
            int q = q0 + ty * 4 + i;
            float val = m ? (acc[i][j] * 0.125f + bias) : -INFINITY;
            Wbh[(size_t)q * NK + k] = val;
        }
    }
}

// ---------------- in-place row softmax over NK=1024 ------------------------
__global__ void softmax_kernel(float* __restrict__ W)
{
    float* p = W + (size_t)blockIdx.x * NK;
    const int tid = threadIdx.x;
    float v[4];
    float m = -INFINITY;
    #pragma unroll
    for (int i = 0; i < 4; i++) { v[i] = p[tid + i * 256]; m = fmaxf(m, v[i]); }

    __shared__ float red[256];
    red[tid] = m; __syncthreads();
    for (int s = 128; s > 0; s >>= 1) {
        if (tid < s) red[tid] = fmaxf(red[tid], red[tid + s]);
        __syncthreads();
    }
    m = red[0]; __syncthreads();

    float sum = 0.f;
    #pragma unroll
    for (int i = 0; i < 4; i++) { v[i] = __expf(v[i] - m); sum += v[i]; }
    red[tid] = sum; __syncthreads();
    for (int s = 128; s > 0; s >>= 1) {
        if (tid < s) red[tid] += red[tid + s];
        __syncthreads();
    }
    float inv = 1.0f / red[0];
    #pragma unroll
    for (int i = 0; i < 4; i++) p[tid + i * 256] = v[i] * inv;
}

// ---------------- ctx = w @ Vh per (b,h): [NQ,NK] x [NK,DHEAD] -------------
__global__ void ctx_kernel(const float* __restrict__ W,
                           const float* __restrict__ V,
                           float* __restrict__ ctx)
{
    const int bh = blockIdx.z;
    const int b  = bh / NHEAD, h = bh % NHEAD;
    const float* Ap = W + (size_t)bh * NQ * NK;                  // lda = NK
    const float* Bp = V + (size_t)b * NK * DMODEL + h * DHEAD;   // ldb = DMODEL
    float*       Cp = ctx + (size_t)b * NQ * DMODEL + h * DHEAD; // ldc = DMODEL
    const int q0 = blockIdx.y * 64;

    __shared__ float As[16][64];
    __shared__ float Bs[16][64];
    const int tid = threadIdx.x;
    const int tx = tid & 15, ty = tid >> 4;

    float acc[4][4] = {};
    for (int k0 = 0; k0 < NK; k0 += 16) {
        {
            int r  = tid >> 2;
            int c4 = (tid & 3) << 2;
            float4 v = *reinterpret_cast<const float4*>(
                &Ap[(size_t)(q0 + r) * NK + k0 + c4]);
            As[c4 + 0][r] = v.x; As[c4 + 1][r] = v.y;
            As[c4 + 2][r] = v.z; As[c4 + 3][r] = v.w;
        }
        {
            int r  = tid >> 4;
            int c4 = (tid & 15) << 2;
            float4 v = *reinterpret_cast<const float4*>(
                &Bp[(size_t)(k0 + r) * DMODEL + c4]);
            *reinterpret_cast<float4*>(&Bs[r][c4]) = v;
        }
        __syncthreads();
        #pragma unroll
        for (int kk = 0; kk < 16; kk++) {
            float4 a = *reinterpret_cast<const float4*>(&As[kk][ty * 4]);
            float4 bb = *reinterpret_cast<const float4*>(&Bs[kk][tx * 4]);
            const float av[4] = {a.x, a.y, a.z, a.w};
            const float bv[4] = {bb.x, bb.y, bb.z, bb.w};
            #pragma unroll
            for (int i = 0; i < 4; i++)
                #pragma unroll
                for (int j = 0; j < 4; j++)
                    acc[i][j] += av[i] * bv[j];
        }
        __syncthreads();
    }
    #pragma unroll
    for (int i = 0; i < 4; i++) {
        int q = q0 + ty * 4 + i;
        #pragma unroll
        for (int j = 0; j < 4; j++)
            Cp[(size_t)q * DMODEL + tx * 4 + j] = acc[i][j];
    }
}

// ---------------- fused residual + LayerNorm over D=512 --------------------
__global__ void ln_kernel(const float* __restrict__ x,
                          const float* __restrict__ qx,
                          const float* __restrict__ g,
                          const float* __restrict__ beta,
                          float* __restrict__ out)
{
    const int row = blockIdx.x;
    const int tid = threadIdx.x;
    const float* xr = x  + (size_t)row * DMODEL;
    const float* qr = qx + (size_t)row * DMODEL;

    float v0 = xr[tid]       + qr[tid];
    float v1 = xr[tid + 256] + qr[tid + 256];

    __shared__ float red[256];
    red[tid] = v0 + v1; __syncthreads();
    for (int s = 128; s > 0; s >>= 1) {
        if (tid < s) red[tid] += red[tid + s];
        __syncthreads();
    }
    float mu = red[0] * (1.0f / DMODEL);
    __syncthreads();

    float d0 = v0 - mu, d1 = v1 - mu;
    red[tid] = d0 * d0 + d1 * d1; __syncthreads();
    for (int s = 128; s > 0; s >>= 1) {
        if (tid < s) red[tid] += red[tid + s];
        __syncthreads();
    }
    float rs = rsqrtf(red[0] * (1.0f / DMODEL) + LN_EPS);

    out[(size_t)row * DMODEL + tid]       = d0 * rs * g[tid]       + beta[tid];
    out[(size_t)row * DMODEL + tid + 256] = d1 * rs * g[tid + 256] + beta[tid + 256];
}

// ---------------------------------------------------------------------------
extern "C" void kernel_launch(void* const* d_in, const int* in_sizes, int n_in,
                              void* d_out, int out_size)
{
    const float* qx     = (const float*)d_in[0];
    const float* kx     = (const float*)d_in[1];
    // mask_q (d_in[2]) is unused by the reference
    const int*   mask_k = (const int*)d_in[3];     // bool -> int32 in harness
    const float* log_g  = (const float*)d_in[4];
    const float* Wq     = (const float*)d_in[5];
    const float* bq     = (const float*)d_in[6];
    const float* Wk     = (const float*)d_in[7];
    const float* bk     = (const float*)d_in[8];
    const float* Wv     = (const float*)d_in[9];
    const float* bv     = (const float*)d_in[10];
    const float* Wo     = (const float*)d_in[11];
    const float* bo     = (const float*)d_in[12];
    const float* ln_g   = (const float*)d_in[13];
    const float* ln_b   = (const float*)d_in[14];
    (void)in_sizes; (void)n_in;

    float *Qp, *Kp, *Vp, *ctxp, *xp, *wfb;
    cudaGetSymbolAddress((void**)&Qp,   g_Q);
    cudaGetSymbolAddress((void**)&Kp,   g_K);
    cudaGetSymbolAddress((void**)&Vp,   g_V);
    cudaGetSymbolAddress((void**)&ctxp, g_ctx);
    cudaGetSymbolAddress((void**)&xp,   g_x);
    cudaGetSymbolAddress((void**)&wfb,  g_w_fb);

    const size_t LN_ELEMS = (size_t)BATCH * NQ * DMODEL;         // 2,097,152
    const size_t W_ELEMS  = (size_t)BATCH * NHEAD * NQ * NK;     // 33,554,432
    float* out_ln = (float*)d_out;
    float* Wbuf   = ((size_t)out_size >= LN_ELEMS + W_ELEMS)
                        ? (out_ln + LN_ELEMS) : wfb;

    const dim3 blk(256);

    // Q/K/V projections
    dim3 gproj(DMODEL / 64, (BATCH * NQ) / 64);
    gemm_bias_kernel<<<gproj, blk>>>(qx, Wq, bq, Qp, BATCH * NQ, DMODEL, DMODEL);
    gemm_bias_kernel<<<gproj, blk>>>(kx, Wk, bk, Kp, BATCH * NK, DMODEL, DMODEL);
    gemm_bias_kernel<<<gproj, blk>>>(kx, Wv, bv, Vp, BATCH * NK, DMODEL, DMODEL);

    // attention scores (+bias, +mask) into w buffer
    dim3 gsc(NK / 64, NQ / 64, BATCH * NHEAD);
    scores_kernel<<<gsc, blk>>>(Qp, Kp, mask_k, log_g, Wbuf);

    // row softmax in place
    softmax_kernel<<<BATCH * NHEAD * NQ, 256>>>(Wbuf);

    // ctx = w @ V per head
    dim3 gctx(1, NQ / 64, BATCH * NHEAD);
    ctx_kernel<<<gctx, blk>>>(Wbuf, Vp, ctxp);

    // output projection
    gemm_bias_kernel<<<gproj, blk>>>(ctxp, Wo, bo, xp, BATCH * NQ, DMODEL, DMODEL);

    // residual + LayerNorm
    ln_kernel<<<BATCH * NQ, 256>>>(xp, qx, ln_g, ln_b, out_ln);
}

// round 4
// speedup vs baseline: 1.2497x; 1.2497x over previous
#include <cuda_runtime.h>
#include <math.h>

#define BATCH  4
#define NQ     1024
#define NK     1024
#define DMODEL 512
#define NHEAD  8
#define DHEAD  64
#define LN_EPS 1e-5f

#define SMW 132   // padded smem row width for transposed tiles (conflict-free, 16B-aligned)

// ---------------- scratch (device globals: allocation-free) ----------------
__device__ float g_Q[(size_t)BATCH * NQ * DMODEL];
__device__ float g_K[(size_t)BATCH * NK * DMODEL];
__device__ float g_V[(size_t)BATCH * NK * DMODEL];
__device__ float g_ctx[(size_t)BATCH * NQ * DMODEL];
__device__ float g_x[(size_t)BATCH * NQ * DMODEL];
__device__ float g_w_fb[(size_t)BATCH * NHEAD * NQ * NK];

// Conflict-free transposed tile load: 128 rows x (DCH*4) cols from global
// (row stride ld) into Ts[d][SMW] (transposed). Thread pairs read 32B runs.
template<int DCH>
__device__ __forceinline__ void load_tile_T(const float* __restrict__ gp,
                                            int ld, float* __restrict__ Ts)
{
    constexpr int TOT   = 128 * DCH;      // total float4s
    constexpr int ITERS = TOT / 256;
    constexpr int DHI_MASK = DCH / 2 - 1;
    constexpr int RHI_SHIFT = (DCH == 2) ? 5 : (DCH == 8) ? 7 : 8;  // 5+log2(DCH/2)
    #pragma unroll
    for (int i = 0; i < ITERS; i++) {
        int idx = threadIdx.x + i * 256;
        int dlo = idx & 1;
        int rlo = (idx >> 1) & 15;
        int dhi = (idx >> 5) & DHI_MASK;
        int rhi = idx >> RHI_SHIFT;
        int d   = ((dlo | (dhi << 1)) << 2);
        int row = rlo | (rhi << 4);
        float4 v = *reinterpret_cast<const float4*>(gp + (size_t)row * ld + d);
        float* t = Ts + (size_t)d * SMW + row;
        t[0] = v.x; t[SMW] = v.y; t[2 * SMW] = v.z; t[3 * SMW] = v.w;
    }
}

// ---------------- 128x128x8 sgemm body: C = A@B + bias ---------------------
__device__ __forceinline__ void gemm128_body(const float* __restrict__ A,
                                             const float* __restrict__ B,
                                             const float* __restrict__ bias,
                                             float* __restrict__ C,
                                             int M, int N, int K)
{
    __shared__ float As[8][SMW];
    __shared__ float Bs[8][128];
    const int tid = threadIdx.x;
    const int tx = tid & 15, ty = tid >> 4;
    const int row0 = blockIdx.y * 128;
    const int col0 = blockIdx.x * 128;

    float acc[8][8] = {};
    for (int k0 = 0; k0 < K; k0 += 8) {
        load_tile_T<2>(A + (size_t)row0 * K + k0, K, &As[0][0]);
        {
            int r  = tid >> 5;
            int c4 = (tid & 31) << 2;
            float4 v = *reinterpret_cast<const float4*>(
                &B[(size_t)(k0 + r) * N + col0 + c4]);
            *reinterpret_cast<float4*>(&Bs[r][c4]) = v;
        }
        __syncthreads();
        #pragma unroll
        for (int kk = 0; kk < 8; kk++) {
            float4 a0 = *reinterpret_cast<const float4*>(&As[kk][ty * 4]);
            float4 a1 = *reinterpret_cast<const float4*>(&As[kk][ty * 4 + 64]);
            float4 b0 = *reinterpret_cast<const float4*>(&Bs[kk][tx * 4]);
            float4 b1 = *reinterpret_cast<const float4*>(&Bs[kk][tx * 4 + 64]);
            const float av[8] = {a0.x, a0.y, a0.z, a0.w, a1.x, a1.y, a1.z, a1.w};
            const float bv[8] = {b0.x, b0.y, b0.z, b0.w, b1.x, b1.y, b1.z, b1.w};
            #pragma unroll
            for (int i = 0; i < 8; i++)
                #pragma unroll
                for (int j = 0; j < 8; j++)
                    acc[i][j] += av[i] * bv[j];
        }
        __syncthreads();
    }
    float4 bb0 = *reinterpret_cast<const float4*>(&bias[col0 + tx * 4]);
    float4 bb1 = *reinterpret_cast<const float4*>(&bias[col0 + tx * 4 + 64]);
    const float bv[8] = {bb0.x, bb0.y, bb0.z, bb0.w, bb1.x, bb1.y, bb1.z, bb1.w};
    #pragma unroll
    for (int i = 0; i < 8; i++) {
        int r = row0 + ((i < 4) ? (ty * 4 + i) : (64 + ty * 4 + i - 4));
        float4 o0 = make_float4(acc[i][0] + bv[0], acc[i][1] + bv[1],
                                acc[i][2] + bv[2], acc[i][3] + bv[3]);
        float4 o1 = make_float4(acc[i][4] + bv[4], acc[i][5] + bv[5],
                                acc[i][6] + bv[6], acc[i][7] + bv[7]);
        *reinterpret_cast<float4*>(&C[(size_t)r * N + col0 + tx * 4])      = o0;
        *reinterpret_cast<float4*>(&C[(size_t)r * N + col0 + tx * 4 + 64]) = o1;
    }
}

// fused Q/K/V projection: blockIdx.z selects which projection
__global__ void qkv_kernel(const float* __restrict__ qx, const float* __restrict__ kx,
                           const float* __restrict__ Wq, const float* __restrict__ bq,
                           const float* __restrict__ Wk, const float* __restrict__ bk,
                           const float* __restrict__ Wv, const float* __restrict__ bv,
                           float* __restrict__ Q, float* __restrict__ K,
                           float* __restrict__ V)
{
    int sel = blockIdx.z;
    const float* A    = (sel == 0) ? qx : kx;
    const float* B    = (sel == 0) ? Wq : (sel == 1) ? Wk : Wv;
    const float* bias = (sel == 0) ? bq : (sel == 1) ? bk : bv;
    float*       C    = (sel == 0) ? Q  : (sel == 1) ? K  : V;
    gemm128_body(A, B, bias, C, BATCH * NQ, DMODEL, DMODEL);
}

__global__ void gemm_kernel(const float* __restrict__ A, const float* __restrict__ B,
                            const float* __restrict__ bias, float* __restrict__ C,
                            int M, int N, int K)
{
    gemm128_body(A, B, bias, C, M, N, K);
}

// ------------- scores: S = Qh @ Kh^T / 8 + bias, masked --------------------
// 128x128 tile per block; full dh=64 staged in (dynamic) smem.
__global__ void scores_kernel(const float* __restrict__ Q,
                              const float* __restrict__ Kmat,
                              const int* __restrict__ mask_k,
                              const float* __restrict__ log_g,
                              float* __restrict__ W)
{
    extern __shared__ float sm[];
    float* Qs = sm;                 // [64][SMW]
    float* Ks = sm + 64 * SMW;      // [64][SMW]

    const int bh = blockIdx.z;
    const int b  = bh / NHEAD, h = bh % NHEAD;
    const float* Ap = Q    + (size_t)b * NQ * DMODEL + h * DHEAD;
    const float* Bp = Kmat + (size_t)b * NK * DMODEL + h * DHEAD;
    const int q0 = blockIdx.y * 128;
    const int k0 = blockIdx.x * 128;

    load_tile_T<16>(Ap + (size_t)q0 * DMODEL, DMODEL, Qs);
    load_tile_T<16>(Bp + (size_t)k0 * DMODEL, DMODEL, Ks);
    __syncthreads();

    const int tid = threadIdx.x;
    const int tx = tid & 15, ty = tid >> 4;

    float acc[8][8] = {};
    #pragma unroll 8
    for (int kk = 0; kk < 64; kk++) {
        float4 a0 = *reinterpret_cast<const float4*>(&Qs[kk * SMW + ty * 4]);
        float4 a1 = *reinterpret_cast<const float4*>(&Qs[kk * SMW + ty * 4 + 64]);
        float4 b0 = *reinterpret_cast<const float4*>(&Ks[kk * SMW + tx * 4]);
        float4 b1 = *reinterpret_cast<const float4*>(&Ks[kk * SMW + tx * 4 + 64]);
        const float av[8] = {a0.x, a0.y, a0.z, a0.w, a1.x, a1.y, a1.z, a1.w};
        const float bv[8] = {b0.x, b0.y, b0.z, b0.w, b1.x, b1.y, b1.z, b1.w};
        #pragma unroll
        for (int i = 0; i < 8; i++)
            #pragma unroll
            for (int j = 0; j < 8; j++)
                acc[i][j] += av[i] * bv[j];
    }

    float kb[8]; bool km[8];
    #pragma unroll
    for (int j = 0; j < 8; j++) {
        int col = k0 + ((j < 4) ? (tx * 4 + j) : (64 + tx * 4 + j - 4));
        kb[j] = log_g[b * NK + col];
        km[j] = mask_k[b * NK + col] != 0;
    }
    float* Wbh = W + (size_t)bh * NQ * NK;
    #pragma unroll
    for (int i = 0; i < 8; i++) {
        int q = q0 + ((i < 4) ? (ty * 4 + i) : (64 + ty * 4 + i - 4));
        float o[8];
        #pragma unroll
        for (int j = 0; j < 8; j++)
            o[j] = km[j] ? (acc[i][j] * 0.125f + kb[j]) : -INFINITY;
        *reinterpret_cast<float4*>(&Wbh[(size_t)q * NK + k0 + tx * 4]) =
            make_float4(o[0], o[1], o[2], o[3]);
        *reinterpret_cast<float4*>(&Wbh[(size_t)q * NK + k0 + tx * 4 + 64]) =
            make_float4(o[4], o[5], o[6], o[7]);
    }
}

// ---------------- in-place row softmax over NK=1024 (float4) ---------------
__global__ void softmax_kernel(float* __restrict__ W)
{
    float4* p = reinterpret_cast<float4*>(W + (size_t)blockIdx.x * NK);
    const int tid  = threadIdx.x;
    const int lane = tid & 31, wid = tid >> 5;
    float4 v = p[tid];

    float m = fmaxf(fmaxf(v.x, v.y), fmaxf(v.z, v.w));
    #pragma unroll
    for (int o = 16; o > 0; o >>= 1) m = fmaxf(m, __shfl_xor_sync(~0u, m, o));
    __shared__ float red[8];
    if (lane == 0) red[wid] = m;
    __syncthreads();
    m = red[0];
    #pragma unroll
    for (int i = 1; i < 8; i++) m = fmaxf(m, red[i]);
    __syncthreads();

    v.x = __expf(v.x - m); v.y = __expf(v.y - m);
    v.z = __expf(v.z - m); v.w = __expf(v.w - m);
    float s = v.x + v.y + v.z + v.w;
    #pragma unroll
    for (int o = 16; o > 0; o >>= 1) s += __shfl_xor_sync(~0u, s, o);
    if (lane == 0) red[wid] = s;
    __syncthreads();
    s = red[0];
    #pragma unroll
    for (int i = 1; i < 8; i++) s += red[i];
    float inv = 1.0f / s;
    v.x *= inv; v.y *= inv; v.z *= inv; v.w *= inv;
    p[tid] = v;
}

// ---------------- ctx = w @ Vh per (b,h): 128x64 tile, BK=32 ---------------
__global__ void ctx_kernel(const float* __restrict__ W,
                           const float* __restrict__ V,
                           float* __restrict__ ctx)
{
    __shared__ float Ws[32][SMW];
    __shared__ float Vs[32][68];

    const int bh = blockIdx.z;
    const int b  = bh / NHEAD, h = bh % NHEAD;
    const float* Ap = W   + (size_t)bh * NQ * NK;
    const float* Bp = V   + (size_t)b * NK * DMODEL + h * DHEAD;
    float*       Cp = ctx + (size_t)b * NQ * DMODEL + h * DHEAD;
    const int q0 = blockIdx.y * 128;

    const int tid = threadIdx.x;
    const int tx = tid & 15, ty = tid >> 4;

    float acc[8][4] = {};
    for (int k0 = 0; k0 < NK; k0 += 32) {
        load_tile_T<8>(Ap + (size_t)q0 * NK + k0, NK, &Ws[0][0]);
        #pragma unroll
        for (int i = 0; i < 2; i++) {
            int idx = tid + i * 256;
            int r = idx >> 4, c4 = (idx & 15) << 2;
            float4 v = *reinterpret_cast<const float4*>(
                &Bp[(size_t)(k0 + r) * DMODEL + c4]);
            *reinterpret_cast<float4*>(&Vs[r][c4]) = v;
        }
        __syncthreads();
        #pragma unroll 8
        for (int kk = 0; kk < 32; kk++) {
            float4 a0 = *reinterpret_cast<const float4*>(&Ws[kk][ty * 4]);
            float4 a1 = *reinterpret_cast<const float4*>(&Ws[kk][ty * 4 + 64]);
            float4 bb = *reinterpret_cast<const float4*>(&Vs[kk][tx * 4]);
            const float av[8] = {a0.x, a0.y, a0.z, a0.w, a1.x, a1.y, a1.z, a1.w};
            const float bv[4] = {bb.x, bb.y, bb.z, bb.w};
            #pragma unroll
            for (int i = 0; i < 8; i++)
                #pragma unroll
                for (int j = 0; j < 4; j++)
                    acc[i][j] += av[i] * bv[j];
        }
        __syncthreads();
    }
    #pragma unroll
    for (int i = 0; i < 8; i++) {
        int q = q0 + ((i < 4) ? (ty * 4 + i) : (64 + ty * 4 + i - 4));
        *reinterpret_cast<float4*>(&Cp[(size_t)q * DMODEL + tx * 4]) =
            make_float4(acc[i][0], acc[i][1], acc[i][2], acc[i][3]);
    }
}

// ---------------- fused residual + LayerNorm over D=512 --------------------
__global__ void ln_kernel(const float* __restrict__ x,
                          const float* __restrict__ qx,
                          const float* __restrict__ g,
                          const float* __restrict__ beta,
                          float* __restrict__ out)
{
    const int row = blockIdx.x;
    const int tid = threadIdx.x;
    const float* xr = x  + (size_t)row * DMODEL;
    const float* qr = qx + (size_t)row * DMODEL;

    float v0 = xr[tid]       + qr[tid];
    float v1 = xr[tid + 256] + qr[tid + 256];

    __shared__ float red[256];
    red[tid] = v0 + v1; __syncthreads();
    for (int s = 128; s > 0; s >>= 1) {
        if (tid < s) red[tid] += red[tid + s];
        __syncthreads();
    }
    float mu = red[0] * (1.0f / DMODEL);
    __syncthreads();

    float d0 = v0 - mu, d1 = v1 - mu;
    red[tid] = d0 * d0 + d1 * d1; __syncthreads();
    for (int s = 128; s > 0; s >>= 1) {
        if (tid < s) red[tid] += red[tid + s];
        __syncthreads();
    }
    float rs = rsqrtf(red[0] * (1.0f / DMODEL) + LN_EPS);

    out[(size_t)row * DMODEL + tid]       = d0 * rs * g[tid]       + beta[tid];
    out[(size_t)row * DMODEL + tid + 256] = d1 * rs * g[tid + 256] + beta[tid + 256];
}

// ---------------------------------------------------------------------------
extern "C" void kernel_launch(void* const* d_in, const int* in_sizes, int n_in,
                              void* d_out, int out_size)
{
    const float* qx     = (const float*)d_in[0];
    const float* kx     = (const float*)d_in[1];
    const int*   mask_k = (const int*)d_in[3];     // bool -> int32 in harness
    const float* log_g  = (const float*)d_in[4];
    const float* Wq     = (const float*)d_in[5];
    const float* bq     = (const float*)d_in[6];
    const float* Wk     = (const float*)d_in[7];
    const float* bk     = (const float*)d_in[8];
    const float* Wv     = (const float*)d_in[9];
    const float* bv     = (const float*)d_in[10];
    const float* Wo     = (const float*)d_in[11];
    const float* bo     = (const float*)d_in[12];
    const float* ln_g   = (const float*)d_in[13];
    const float* ln_b   = (const float*)d_in[14];
    (void)in_sizes; (void)n_in;

    float *Qp, *Kp, *Vp, *ctxp, *xp, *wfb;
    cudaGetSymbolAddress((void**)&Qp,   g_Q);
    cudaGetSymbolAddress((void**)&Kp,   g_K);
    cudaGetSymbolAddress((void**)&Vp,   g_V);
    cudaGetSymbolAddress((void**)&ctxp, g_ctx);
    cudaGetSymbolAddress((void**)&xp,   g_x);
    cudaGetSymbolAddress((void**)&wfb,  g_w_fb);

    const size_t LN_ELEMS = (size_t)BATCH * NQ * DMODEL;
    const size_t W_ELEMS  = (size_t)BATCH * NHEAD * NQ * NK;
    float* out_ln = (float*)d_out;
    float* Wbuf   = ((size_t)out_size >= LN_ELEMS + W_ELEMS)
                        ? (out_ln + LN_ELEMS) : wfb;

    const int SMEM_SCORES = 2 * 64 * SMW * sizeof(float);   // ~66KB
    cudaFuncSetAttribute(scores_kernel,
                         cudaFuncAttributeMaxDynamicSharedMemorySize, SMEM_SCORES);

    const dim3 blk(256);

    // fused Q/K/V projections (128x128 tiles)
    dim3 gqkv(DMODEL / 128, (BATCH * NQ) / 128, 3);
    qkv_kernel<<<gqkv, blk>>>(qx, kx, Wq, bq, Wk, bk, Wv, bv, Qp, Kp, Vp);

    // attention scores (+bias, +mask)
    dim3 gsc(NK / 128, NQ / 128, BATCH * NHEAD);
    scores_kernel<<<gsc, blk, SMEM_SCORES>>>(Qp, Kp, mask_k, log_g, Wbuf);

    // row softmax in place
    softmax_kernel<<<BATCH * NHEAD * NQ, 256>>>(Wbuf);

    // ctx = w @ V per head
    dim3 gctx(1, NQ / 128, BATCH * NHEAD);
    ctx_kernel<<<gctx, blk>>>(Wbuf, Vp, ctxp);

    // output projection
    dim3 go(DMODEL / 128, (BATCH * NQ) / 128);
    gemm_kernel<<<go, blk>>>(ctxp, Wo, bo, xp, BATCH * NQ, DMODEL, DMODEL);

    // residual + LayerNorm
    ln_kernel<<<BATCH * NQ, 256>>>(xp, qx, ln_g, ln_b, out_ln);
}